// round 5
// baseline (speedup 1.0000x reference)
#include <cuda_runtime.h>

// Problem constants (fixed shapes from reference)
#define NROWS   65536            // BATCH*SEQ = 64*1024
#define FEATD   512
#define NBINS   32

// Global-pool occurrence counting (reference's int32 semantics drop `env`:
// left_shift(env,32) on int32 == 0 in XLA, so combined == keys).
#define HASH_BITS 17
#define HASH_SZ   (1 << HASH_BITS)
#define DUP_CAP   1024

// ---------------- scratch (device globals; no allocation allowed) ----------
__device__ float g_psum[1024 * 512];
__device__ float g_psq [1024 * 512];
__device__ float g_psum2[16 * 512];
__device__ float g_psq2 [16 * 512];
__device__ float g_Pp  [512 * 32];     // P' = P / sigma   (row-major [feat][bin])
__device__ float g_bias[32];           // bias_j = sum_f mean_f * Pp[f][j]
__device__ unsigned int g_keys[NROWS];
__device__ unsigned long long g_hash[HASH_SZ];  // 0 = empty, else (1<<32)|key
__device__ unsigned int g_hcnt[HASH_SZ];        // total occurrences per slot
__device__ int g_slot[NROWS];                   // row -> slot
__device__ int g_dupn;
__device__ int g_dup[DUP_CAP];                  // rows whose key count > 1

// ---------------------------------------------------------------------------
// Kernel 0: reset hash state (graph replays reuse the globals).
// ---------------------------------------------------------------------------
__global__ void __launch_bounds__(256) zero_kernel() {
    int t = blockIdx.x * 256 + threadIdx.x;     // 0 .. HASH_SZ-1 (512 blocks)
    g_hash[t] = 0ull;
    g_hcnt[t] = 0u;
    if (t == 0) g_dupn = 0;
}

// ---------------------------------------------------------------------------
// Kernel 1: per-feature partial sums / sums of squares.
// grid 1024 blocks x 128 threads; block b handles rows [b*64, b*64+64).
// thread t owns feature quad [4t, 4t+4). Fully coalesced float4 streaming.
// ---------------------------------------------------------------------------
__global__ void __launch_bounds__(128) sums_kernel(const float* __restrict__ x) {
    int t = threadIdx.x;
    const float4* xg = (const float4*)x + (size_t)blockIdx.x * 64 * 128 + t;
    float sx = 0.f, sy = 0.f, sz = 0.f, sw = 0.f;
    float qx = 0.f, qy = 0.f, qz = 0.f, qw = 0.f;
#pragma unroll 8
    for (int r = 0; r < 64; r++) {
        float4 v = xg[(size_t)r * 128];
        sx += v.x; sy += v.y; sz += v.z; sw += v.w;
        qx = fmaf(v.x, v.x, qx); qy = fmaf(v.y, v.y, qy);
        qz = fmaf(v.z, v.z, qz); qw = fmaf(v.w, v.w, qw);
    }
    ((float4*)g_psum)[blockIdx.x * 128 + t] = make_float4(sx, sy, sz, sw);
    ((float4*)g_psq )[blockIdx.x * 128 + t] = make_float4(qx, qy, qz, qw);
}

// ---------------------------------------------------------------------------
// Kernel 1.5: fold 1024 partials -> 16 partials.
// grid 16 x 512: thread T -> (p = T/512, f = T%512), sums 64 input blocks.
// ---------------------------------------------------------------------------
__global__ void __launch_bounds__(512) midreduce_kernel() {
    int T = blockIdx.x * 512 + threadIdx.x;     // 0 .. 8191
    int p = T >> 9;
    int f = T & 511;
    float s = 0.f, q = 0.f;
#pragma unroll 8
    for (int i = 0; i < 64; i++) {
        int idx = ((p * 64 + i) << 9) + f;
        s += g_psum[idx];
        q += g_psq [idx];
    }
    g_psum2[T] = s;
    g_psq2 [T] = q;
}

// ---------------------------------------------------------------------------
// Kernel 2: finalize Welford-merged stats (fp64), build P' and bias.
// single block, 512 threads (thread f = feature).
// ---------------------------------------------------------------------------
__global__ void __launch_bounds__(512) stats_kernel(const float* __restrict__ P) {
    int f = threadIdx.x;
    double s = 0.0, q = 0.0;
#pragma unroll
    for (int b = 0; b < 16; b++) {
        s += (double)g_psum2[(b << 9) + f];
        q += (double)g_psq2 [(b << 9) + f];
    }
    const double Nd = (double)NROWS;
    double bm  = s / Nd;                                   // batch mean
    double bv  = (q - Nd * bm * bm) / (Nd - 1.0);          // unbiased var (ddof=1)
    double tot = 1e-4 + Nd;
    double mean = bm * Nd / tot;
    double M2   = 1e-4 + bv * Nd + bm * bm * 1e-4 * Nd / tot;
    double var  = M2 / tot;
    float inv_sigma = (float)(1.0 / sqrt(var + 1e-8));
    float meanf     = (float)mean;

    float pp[NBINS];
#pragma unroll
    for (int j = 0; j < NBINS; j++) {
        pp[j] = P[f * NBINS + j] * inv_sigma;
        g_Pp[f * NBINS + j] = pp[j];
    }

    // bias_j = sum_f meanf * pp[f][j] — deterministic shuffle + shared reduce
    __shared__ float wsum[16][NBINS];
    int lane = f & 31, w = f >> 5;
#pragma unroll
    for (int j = 0; j < NBINS; j++) {
        float v = meanf * pp[j];
#pragma unroll
        for (int off = 16; off > 0; off >>= 1)
            v += __shfl_down_sync(0xffffffffu, v, off);
        if (lane == 0) wsum[w][j] = v;
    }
    __syncthreads();
    if (f < NBINS) {
        float b = 0.f;
#pragma unroll
        for (int w2 = 0; w2 < 16; w2++) b += wsum[w2][f];
        g_bias[f] = b;
    }
}

// ---------------------------------------------------------------------------
// Kernel 3: projection + sign-bit keys (fast fp32 path, packed f32x2 FMA).
//   key[i] = ballot_j( x[i] . Pp[:,j] - bias_j > 0 )
// ---------------------------------------------------------------------------
#define P3_CH   64
#define P3_NW   8
#define P3_RB   8
#define P3_NBATCH (NROWS / P3_RB)    // 8192

__global__ void __launch_bounds__(256, 2) proj_kernel(const float* __restrict__ x) {
    __shared__ float xs[P3_RB * FEATD];            // 16 KB row tile
    __shared__ float psum[P3_RB][P3_NW][NBINS];    // 8 KB partials
    __shared__ float sbias[NBINS];

    int tid  = threadIdx.x;
    int warp = tid >> 5;
    int lane = tid & 31;

    if (tid < NBINS) sbias[tid] = g_bias[tid];

    // register-resident Pp chunk: ppd[i] = (Pp[k0+2i][lane], Pp[k0+2i+1][lane])
    unsigned long long ppd[P3_CH / 2];
    int k0 = warp * P3_CH;
#pragma unroll
    for (int i = 0; i < P3_CH / 2; i++) {
        float a = g_Pp[(k0 + 2 * i)     * NBINS + lane];
        float b = g_Pp[(k0 + 2 * i + 1) * NBINS + lane];
        asm("mov.b64 %0, {%1, %2};" : "=l"(ppd[i]) : "f"(a), "f"(b));
    }

    for (int batch = blockIdx.x; batch < P3_NBATCH; batch += gridDim.x) {
        __syncthreads();   // xs/psum reuse guard
        const float4* xg  = (const float4*)(x + (size_t)batch * P3_RB * FEATD);
        float4*       xs4 = (float4*)xs;
#pragma unroll
        for (int i = 0; i < 4; i++) xs4[tid + 256 * i] = xg[tid + 256 * i];
        __syncthreads();

#pragma unroll
        for (int r = 0; r < P3_RB; r++) {
            const ulonglong2* xp = (const ulonglong2*)(xs + r * FEATD + k0);
            unsigned long long a0 = 0ull, a1 = 0ull;   // (0.f,0.f) packed
#pragma unroll
            for (int i = 0; i < P3_CH / 4; i++) {
                ulonglong2 v = xp[i];                   // LDS.128 broadcast
                asm("fma.rn.f32x2 %0, %1, %2, %0;"
                    : "+l"(a0) : "l"(v.x), "l"(ppd[2 * i]));
                asm("fma.rn.f32x2 %0, %1, %2, %0;"
                    : "+l"(a1) : "l"(v.y), "l"(ppd[2 * i + 1]));
            }
            unsigned long long at;
            asm("add.rn.f32x2 %0, %1, %2;" : "=l"(at) : "l"(a0), "l"(a1));
            float lo, hi;
            asm("mov.b64 {%0, %1}, %2;" : "=f"(lo), "=f"(hi) : "l"(at));
            psum[r][warp][lane] = lo + hi;
        }
        __syncthreads();

        // warp r reduces row r across the 8 K-chunks, then ballots the key
        {
            int r = warp;
            int row = batch * P3_RB + r;
            float s = 0.f;
#pragma unroll
            for (int c = 0; c < P3_NW; c++) s += psum[r][c][lane];
            unsigned key = __ballot_sync(0xffffffffu, s > sbias[lane]);
            if (lane == 0) g_keys[row] = key;
        }
    }
}

// ---------------------------------------------------------------------------
// Kernel 4a: hash-insert all keys; count total occurrences per key.
// Same key always resolves to the same slot (tagged 64-bit CAS, linear probe).
// ---------------------------------------------------------------------------
__global__ void __launch_bounds__(256) insert_kernel() {
    int i = blockIdx.x * 256 + threadIdx.x;     // 256 blocks -> 65536 rows
    unsigned key = g_keys[i];
    unsigned long long tag = (1ull << 32) | (unsigned long long)key;
    unsigned h = (key * 2654435761u) >> (32 - HASH_BITS);
    for (;;) {
        unsigned long long prev = atomicCAS(&g_hash[h], 0ull, tag);
        if (prev == 0ull || prev == tag) {
            atomicAdd(&g_hcnt[h], 1u);
            g_slot[i] = (int)h;
            break;
        }
        h = (h + 1) & (HASH_SZ - 1);
    }
}

// ---------------------------------------------------------------------------
// Kernel 4b: emit rewards for unique keys (count==1 -> 1.0); collect dup rows.
// ---------------------------------------------------------------------------
__global__ void __launch_bounds__(256) emit_kernel(float* __restrict__ out) {
    int i = blockIdx.x * 256 + threadIdx.x;
    if (g_hcnt[g_slot[i]] == 1u) {
        out[i] = 1.0f;
    } else {
        int d = atomicAdd(&g_dupn, 1);
        if (d < DUP_CAP) g_dup[d] = i;
    }
}

// ---------------------------------------------------------------------------
// Kernel 4c: exact occurrence rank for duplicated rows (rare; ~2 expected).
// One block per dup row: occ = #{ j <= i : key_j == key_i }.
// ---------------------------------------------------------------------------
__global__ void __launch_bounds__(256) dupfix_kernel(float* __restrict__ out) {
    __shared__ int red[256];
    int d = blockIdx.x;
    if (d >= g_dupn) return;
    int i = g_dup[d];
    unsigned key = g_keys[i];
    int t = threadIdx.x;
    int c = 0;
    for (int j = t; j <= i; j += 256) c += (g_keys[j] == key) ? 1 : 0;
    red[t] = c;
    __syncthreads();
#pragma unroll
    for (int off = 128; off > 0; off >>= 1) {
        if (t < off) red[t] += red[t + off];
        __syncthreads();
    }
    if (t == 0) out[i] = rsqrtf((float)red[0]);
}

// ---------------------------------------------------------------------------
extern "C" void kernel_launch(void* const* d_in, const int* in_sizes, int n_in,
                              void* d_out, int out_size) {
    const float* x = (const float*)d_in[0];   // features  [64,1024,512]
    const float* P = (const float*)d_in[1];   // projection [512,32]
    if (n_in >= 2 && in_sizes[0] < in_sizes[1]) {   // defensive order check
        const float* t = x; x = P; P = t;
    }
    float* out = (float*)d_out;

    zero_kernel     <<<HASH_SZ / 256, 256>>>();
    sums_kernel     <<<1024, 128>>>(x);
    midreduce_kernel<<<16,   512>>>();
    stats_kernel    <<<1,    512>>>(P);
    proj_kernel     <<<304,  256>>>(x);
    insert_kernel   <<<NROWS / 256, 256>>>();
    emit_kernel     <<<NROWS / 256, 256>>>(out);
    dupfix_kernel   <<<DUP_CAP, 256>>>(out);
}

// round 6
// speedup vs baseline: 1.2098x; 1.2098x over previous
#include <cuda_runtime.h>

// Problem constants (fixed shapes from reference)
#define NROWS   65536            // BATCH*SEQ = 64*1024
#define FEATD   512
#define NBINS   32

// Global-pool occurrence counting (reference's int32 semantics drop `env`:
// left_shift(env,32) on int32 == 0 in XLA, so combined == keys).
#define HASH_BITS 17
#define HASH_SZ   (1 << HASH_BITS)
#define DUP_CAP   1024

// ---------------- scratch (device globals; no allocation allowed) ----------
__device__ float g_psum[1024 * 512];
__device__ float g_psq [1024 * 512];
__device__ float g_psum2[16 * 512];
__device__ float g_psq2 [16 * 512];
__device__ float g_meanf[FEATD];
__device__ float g_isig [FEATD];
__device__ float g_Pp  [512 * 32];     // P' = P / sigma   (row-major [feat][bin])
__device__ float g_biasp[16 * 32];     // per-block bias partials
__device__ unsigned int g_keys[NROWS];
__device__ unsigned long long g_hash[HASH_SZ];  // 0 = empty, else (1<<32)|key
__device__ unsigned int g_hcnt[HASH_SZ];        // total occurrences per slot
__device__ int g_slot[NROWS];                   // row -> slot
__device__ int g_dupn;
__device__ int g_dup[DUP_CAP];                  // rows whose key count > 1

// ---------------------------------------------------------------------------
// Kernel 0: reset hash state (graph replays reuse the globals).
// ---------------------------------------------------------------------------
__global__ void __launch_bounds__(256) zero_kernel() {
    int t = blockIdx.x * 256 + threadIdx.x;     // 0 .. HASH_SZ-1 (512 blocks)
    g_hash[t] = 0ull;
    g_hcnt[t] = 0u;
    if (t == 0) g_dupn = 0;
}

// ---------------------------------------------------------------------------
// Kernel 1: per-feature partial sums / sums of squares.
// grid 1024 blocks x 128 threads; block b handles rows [b*64, b*64+64).
// thread t owns feature quad [4t, 4t+4). Fully coalesced float4 streaming.
// ---------------------------------------------------------------------------
__global__ void __launch_bounds__(128) sums_kernel(const float* __restrict__ x) {
    int t = threadIdx.x;
    const float4* xg = (const float4*)x + (size_t)blockIdx.x * 64 * 128 + t;
    float sx = 0.f, sy = 0.f, sz = 0.f, sw = 0.f;
    float qx = 0.f, qy = 0.f, qz = 0.f, qw = 0.f;
#pragma unroll 8
    for (int r = 0; r < 64; r++) {
        float4 v = xg[(size_t)r * 128];
        sx += v.x; sy += v.y; sz += v.z; sw += v.w;
        qx = fmaf(v.x, v.x, qx); qy = fmaf(v.y, v.y, qy);
        qz = fmaf(v.z, v.z, qz); qw = fmaf(v.w, v.w, qw);
    }
    ((float4*)g_psum)[blockIdx.x * 128 + t] = make_float4(sx, sy, sz, sw);
    ((float4*)g_psq )[blockIdx.x * 128 + t] = make_float4(qx, qy, qz, qw);
}

// ---------------------------------------------------------------------------
// Kernel 1.5: fold 1024 partials -> 16 partials.
// grid 16 x 512: thread T -> (p = T/512, f = T%512), sums 64 input blocks.
// ---------------------------------------------------------------------------
__global__ void __launch_bounds__(512) midreduce_kernel() {
    int T = blockIdx.x * 512 + threadIdx.x;     // 0 .. 8191
    int p = T >> 9;
    int f = T & 511;
    float s = 0.f, q = 0.f;
#pragma unroll 8
    for (int i = 0; i < 64; i++) {
        int idx = ((p * 64 + i) << 9) + f;
        s += g_psum[idx];
        q += g_psq [idx];
    }
    g_psum2[T] = s;
    g_psq2 [T] = q;
}

// ---------------------------------------------------------------------------
// Kernel 2a: per-feature mean / inv-sigma. grid 4 x 128, thread = feature.
// All reads coalesced; no fp64 div/sqrt (reciprocal constants + NR rsqrt).
// ---------------------------------------------------------------------------
__global__ void __launch_bounds__(128) stats_kernel() {
    int f = blockIdx.x * 128 + threadIdx.x;     // 0 .. 511
    float sp[16], qp[16];
#pragma unroll
    for (int b = 0; b < 16; b++) {
        sp[b] = g_psum2[(b << 9) + f];
        qp[b] = g_psq2 [(b << 9) + f];
    }
    double s = 0.0, q = 0.0;
#pragma unroll
    for (int b = 0; b < 16; b++) { s += (double)sp[b]; q += (double)qp[b]; }

    const double Nd      = 65536.0;
    const double INV_N   = 1.0 / 65536.0;
    const double INV_NM1 = 1.0 / 65535.0;
    const double INV_TOT = 1.0 / 65536.0001;           // 1/(1e-4 + N)
    const double RATIO   = 65536.0 * INV_TOT;          // N/tot
    const double C1      = 1e-4 * 65536.0 * INV_TOT;   // eps*N/tot

    double bm   = s * INV_N;
    double bv   = (q - Nd * bm * bm) * INV_NM1;        // unbiased var (ddof=1)
    double mean = bm * RATIO;
    double var  = (1e-4 + bv * Nd + bm * bm * C1) * INV_TOT;
    double v    = var + 1e-8;
    // inv-sigma via fp32 rsqrt + one fp64 Newton step (rel err ~3e-14)
    double r = (double)rsqrtf((float)v);
    r = r * (1.5 - 0.5 * v * r * r);
    g_meanf[f] = (float)mean;
    g_isig [f] = (float)r;
}

// ---------------------------------------------------------------------------
// Kernel 2b: build Pp (element-indexed, fully coalesced) + bias partials.
// grid 16 x 1024: element e = blockIdx*1024 + tid; j = e & 31 == tid & 31.
// Deterministic shared-memory reduce (no float atomics).
// ---------------------------------------------------------------------------
__global__ void __launch_bounds__(1024) pp_kernel(const float* __restrict__ P) {
    __shared__ float s[32][33];
    int tid = threadIdx.x;
    int e   = blockIdx.x * 1024 + tid;
    int f   = e >> 5;
    float pp = P[e] * g_isig[f];
    g_Pp[e] = pp;
    s[tid >> 5][tid & 31] = g_meanf[f] * pp;
    __syncthreads();
    if (tid < 32) {
        float b = 0.f;
#pragma unroll
        for (int w = 0; w < 32; w++) b += s[w][tid];
        g_biasp[blockIdx.x * 32 + tid] = b;
    }
}

// ---------------------------------------------------------------------------
// Kernel 3: projection + sign-bit keys (fast fp32 path, packed f32x2 FMA).
//   key[i] = ballot_j( x[i] . Pp[:,j] - bias_j > 0 )
// Each block folds the 16 bias partials itself (512 L2-hit loads, free).
// ---------------------------------------------------------------------------
#define P3_CH   64
#define P3_NW   8
#define P3_RB   8
#define P3_NBATCH (NROWS / P3_RB)    // 8192

__global__ void __launch_bounds__(256, 2) proj_kernel(const float* __restrict__ x) {
    __shared__ float xs[P3_RB * FEATD];            // 16 KB row tile
    __shared__ float psum[P3_RB][P3_NW][NBINS];    // 8 KB partials
    __shared__ float sbias[NBINS];

    int tid  = threadIdx.x;
    int warp = tid >> 5;
    int lane = tid & 31;

    if (tid < NBINS) {
        float b = 0.f;
#pragma unroll
        for (int p = 0; p < 16; p++) b += g_biasp[p * 32 + tid];
        sbias[tid] = b;
    }

    // register-resident Pp chunk: ppd[i] = (Pp[k0+2i][lane], Pp[k0+2i+1][lane])
    unsigned long long ppd[P3_CH / 2];
    int k0 = warp * P3_CH;
#pragma unroll
    for (int i = 0; i < P3_CH / 2; i++) {
        float a = g_Pp[(k0 + 2 * i)     * NBINS + lane];
        float b = g_Pp[(k0 + 2 * i + 1) * NBINS + lane];
        asm("mov.b64 %0, {%1, %2};" : "=l"(ppd[i]) : "f"(a), "f"(b));
    }

    for (int batch = blockIdx.x; batch < P3_NBATCH; batch += gridDim.x) {
        __syncthreads();   // xs/psum reuse guard
        const float4* xg  = (const float4*)(x + (size_t)batch * P3_RB * FEATD);
        float4*       xs4 = (float4*)xs;
#pragma unroll
        for (int i = 0; i < 4; i++) xs4[tid + 256 * i] = xg[tid + 256 * i];
        __syncthreads();

#pragma unroll
        for (int r = 0; r < P3_RB; r++) {
            const ulonglong2* xp = (const ulonglong2*)(xs + r * FEATD + k0);
            unsigned long long a0 = 0ull, a1 = 0ull;   // (0.f,0.f) packed
#pragma unroll
            for (int i = 0; i < P3_CH / 4; i++) {
                ulonglong2 v = xp[i];                   // LDS.128 broadcast
                asm("fma.rn.f32x2 %0, %1, %2, %0;"
                    : "+l"(a0) : "l"(v.x), "l"(ppd[2 * i]));
                asm("fma.rn.f32x2 %0, %1, %2, %0;"
                    : "+l"(a1) : "l"(v.y), "l"(ppd[2 * i + 1]));
            }
            unsigned long long at;
            asm("add.rn.f32x2 %0, %1, %2;" : "=l"(at) : "l"(a0), "l"(a1));
            float lo, hi;
            asm("mov.b64 {%0, %1}, %2;" : "=f"(lo), "=f"(hi) : "l"(at));
            psum[r][warp][lane] = lo + hi;
        }
        __syncthreads();

        // warp r reduces row r across the 8 K-chunks, then ballots the key
        {
            int r = warp;
            int row = batch * P3_RB + r;
            float s = 0.f;
#pragma unroll
            for (int c = 0; c < P3_NW; c++) s += psum[r][c][lane];
            unsigned key = __ballot_sync(0xffffffffu, s > sbias[lane]);
            if (lane == 0) g_keys[row] = key;
        }
    }
}

// ---------------------------------------------------------------------------
// Kernel 4a: hash-insert all keys; count total occurrences per key.
// Same key always resolves to the same slot (tagged 64-bit CAS, linear probe).
// ---------------------------------------------------------------------------
__global__ void __launch_bounds__(256) insert_kernel() {
    int i = blockIdx.x * 256 + threadIdx.x;     // 256 blocks -> 65536 rows
    unsigned key = g_keys[i];
    unsigned long long tag = (1ull << 32) | (unsigned long long)key;
    unsigned h = (key * 2654435761u) >> (32 - HASH_BITS);
    for (;;) {
        unsigned long long prev = atomicCAS(&g_hash[h], 0ull, tag);
        if (prev == 0ull || prev == tag) {
            atomicAdd(&g_hcnt[h], 1u);
            g_slot[i] = (int)h;
            break;
        }
        h = (h + 1) & (HASH_SZ - 1);
    }
}

// ---------------------------------------------------------------------------
// Kernel 4b: emit rewards for unique keys (count==1 -> 1.0); collect dup rows.
// ---------------------------------------------------------------------------
__global__ void __launch_bounds__(256) emit_kernel(float* __restrict__ out) {
    int i = blockIdx.x * 256 + threadIdx.x;
    if (g_hcnt[g_slot[i]] == 1u) {
        out[i] = 1.0f;
    } else {
        int d = atomicAdd(&g_dupn, 1);
        if (d < DUP_CAP) g_dup[d] = i;
    }
}

// ---------------------------------------------------------------------------
// Kernel 4c: exact occurrence rank for duplicated rows (rare; ~2 expected).
// One block per dup row: occ = #{ j <= i : key_j == key_i }.
// ---------------------------------------------------------------------------
__global__ void __launch_bounds__(256) dupfix_kernel(float* __restrict__ out) {
    __shared__ int red[256];
    int d = blockIdx.x;
    if (d >= g_dupn) return;
    int i = g_dup[d];
    unsigned key = g_keys[i];
    int t = threadIdx.x;
    int c = 0;
    for (int j = t; j <= i; j += 256) c += (g_keys[j] == key) ? 1 : 0;
    red[t] = c;
    __syncthreads();
#pragma unroll
    for (int off = 128; off > 0; off >>= 1) {
        if (t < off) red[t] += red[t + off];
        __syncthreads();
    }
    if (t == 0) out[i] = rsqrtf((float)red[0]);
}

// ---------------------------------------------------------------------------
extern "C" void kernel_launch(void* const* d_in, const int* in_sizes, int n_in,
                              void* d_out, int out_size) {
    const float* x = (const float*)d_in[0];   // features  [64,1024,512]
    const float* P = (const float*)d_in[1];   // projection [512,32]
    if (n_in >= 2 && in_sizes[0] < in_sizes[1]) {   // defensive order check
        const float* t = x; x = P; P = t;
    }
    float* out = (float*)d_out;

    zero_kernel     <<<HASH_SZ / 256, 256>>>();
    sums_kernel     <<<1024, 128>>>(x);
    midreduce_kernel<<<16,   512>>>();
    stats_kernel    <<<4,    128>>>();
    pp_kernel       <<<16,   1024>>>(P);
    proj_kernel     <<<304,  256>>>(x);
    insert_kernel   <<<NROWS / 256, 256>>>();
    emit_kernel     <<<NROWS / 256, 256>>>(out);
    dupfix_kernel   <<<DUP_CAP, 256>>>(out);
}